// round 3
// baseline (speedup 1.0000x reference)
#include <cuda_runtime.h>

// Problem constants
#define CD    1024   // d_model
#define TQN   1024   // query tokens
#define TKN   8192   // key tokens
#define NH    16     // heads
#define HD    64     // head dim
#define NKEY  512    // keys per head after HEPOS gather (TKN/STRIDE)

// ---------------------------------------------------------------------------
// Scratch (device globals; runtime allocation is forbidden)
// ---------------------------------------------------------------------------
__device__ __align__(256) float g_Qp[TQN * CD];          // 4 MB  Q projection
__device__ __align__(256) float g_Kg[NH * NKEY * HD];    // 2 MB  gathered/projected K, [h][j][d]
__device__ __align__(256) float g_Vg[NH * NKEY * HD];    // 2 MB  gathered/projected V, [h][j][d]
__device__ __align__(256) float g_AO[TQN * CD];          // 4 MB  attention output (heads concat)

// ---------------------------------------------------------------------------
// Generic NT GEMM: C[m,n] = alpha * sum_k A[m*rowMulA, k] * B[n*rowMulB, k] (+bias[n])
// rowMul implements the HEPOS stride-16 row gather. 256 threads, TM x TN tiles.
// ---------------------------------------------------------------------------
template<int BM, int BN, int BK, int TM, int TN>
__global__ __launch_bounds__(256)
void gemm_nt(const float* __restrict__ A, int lda, long aZ, int rowMulA,
             const float* __restrict__ B, int ldb, long bZ,
             const float* __restrict__ bias, int biasZ,
             float alpha,
             float* __restrict__ C, int ldc, long cZ,
             int K)
{
    constexpr int NT = (BM / TM) * (BN / TN);
    static_assert(NT == 256, "thread count mismatch");
    __shared__ float As[BK][BM];
    __shared__ float Bs[BK][BN];

    const int z = blockIdx.z;
    A += z * aZ;
    B += z * bZ;
    C += z * cZ;
    if (bias) bias += (long)z * biasZ;

    const int m0 = blockIdx.y * BM;
    const int n0 = blockIdx.x * BN;
    const int tid = threadIdx.x;
    const int tcol = tid % (BN / TN);
    const int trow = tid / (BN / TN);

    float acc[TM][TN];
    #pragma unroll
    for (int i = 0; i < TM; i++)
        #pragma unroll
        for (int j = 0; j < TN; j++) acc[i][j] = 0.f;

    for (int k0 = 0; k0 < K; k0 += BK) {
        for (int i = tid; i < (BM * BK) / 4; i += NT) {
            int r = i / (BK / 4);
            int c = (i % (BK / 4)) * 4;
            float4 t = *(const float4*)(A + (long)(m0 + r) * rowMulA * lda + (k0 + c));
            As[c + 0][r] = t.x; As[c + 1][r] = t.y;
            As[c + 2][r] = t.z; As[c + 3][r] = t.w;
        }
        for (int i = tid; i < (BN * BK) / 4; i += NT) {
            int r = i / (BK / 4);
            int c = (i % (BK / 4)) * 4;
            float4 t = *(const float4*)(B + (long)(n0 + r) * ldb + (k0 + c));
            Bs[c + 0][r] = t.x; Bs[c + 1][r] = t.y;
            Bs[c + 2][r] = t.z; Bs[c + 3][r] = t.w;
        }
        __syncthreads();

        #pragma unroll
        for (int kk = 0; kk < BK; kk++) {
            float a[TM], b[TN];
            #pragma unroll
            for (int i = 0; i < TM; i += 4)
                *(float4*)&a[i] = *(const float4*)&As[kk][trow * TM + i];
            #pragma unroll
            for (int j = 0; j < TN; j += 4)
                *(float4*)&b[j] = *(const float4*)&Bs[kk][tcol * TN + j];
            #pragma unroll
            for (int i = 0; i < TM; i++)
                #pragma unroll
                for (int j = 0; j < TN; j++)
                    acc[i][j] = fmaf(a[i], b[j], acc[i][j]);
        }
        __syncthreads();
    }

    #pragma unroll
    for (int i = 0; i < TM; i++) {
        int m = m0 + trow * TM + i;
        #pragma unroll
        for (int j = 0; j < TN; j++) {
            int n = n0 + tcol * TN + j;
            float vv = acc[i][j] * alpha;
            if (bias) vv += bias[n];
            C[(long)m * ldc + n] = vv;
        }
    }
}

// ---------------------------------------------------------------------------
// Fused attention per head: S = 0.125 * Q.K^T, online softmax, O = P.V.
// Block = (64 queries x 1 head), 256 threads, 4 key chunks of 128.
// Thread row assignment (trow = tid>>4, rows trow*4+i) is IDENTICAL in both
// GEMMs, so softmax stats (m, s, f) stay in registers across phases.
// ---------------------------------------------------------------------------
__global__ __launch_bounds__(256, 2)
void attn_fused(const float* __restrict__ Qp, const float* __restrict__ Kg,
                const float* __restrict__ Vg, float* __restrict__ AO)
{
    extern __shared__ float smem[];
    float* As = smem;            // [d=64][q=64]   Q tile, k-major        16 KB
    float* sB = smem + 4096;     // K chunk [d=64][key=128] then V [128][64]  32 KB
    float* Ps = smem + 12288;    // [key=128][q=64] probabilities         32 KB

    const int h   = blockIdx.y;
    const int q0  = blockIdx.x * 64;
    const int tid = threadIdx.x;
    const int tc  = tid & 15;    // 16 cols of threads
    const int tr  = tid >> 4;    // 16 rows of threads

    const float* Qb = Qp + (long)q0 * CD + h * HD;
    const float* Kb = Kg + (long)h * NKEY * HD;
    const float* Vb = Vg + (long)h * NKEY * HD;

    // Stage Q tile transposed: As[d][q]
    for (int i = tid; i < 64 * 16; i += 256) {
        int r = i >> 4;            // query row
        int c = (i & 15) << 2;     // d
        float4 t = *(const float4*)(Qb + (long)r * CD + c);
        As[(c + 0) * 64 + r] = t.x; As[(c + 1) * 64 + r] = t.y;
        As[(c + 2) * 64 + r] = t.z; As[(c + 3) * 64 + r] = t.w;
    }

    float m_i[4], s_i[4], acc2[4][4];
    #pragma unroll
    for (int i = 0; i < 4; i++) {
        m_i[i] = -1e30f; s_i[i] = 0.f;
        #pragma unroll
        for (int j = 0; j < 4; j++) acc2[i][j] = 0.f;
    }

    for (int c0 = 0; c0 < NKEY; c0 += 128) {
        __syncthreads();  // previous iteration's sB/Ps readers are done
        // Stage K chunk transposed: sB[d][key]
        for (int i = tid; i < 128 * 16; i += 256) {
            int r = i >> 4;            // key
            int c = (i & 15) << 2;     // d
            float4 t = *(const float4*)(Kb + (long)(c0 + r) * HD + c);
            sB[(c + 0) * 128 + r] = t.x; sB[(c + 1) * 128 + r] = t.y;
            sB[(c + 2) * 128 + r] = t.z; sB[(c + 3) * 128 + r] = t.w;
        }
        __syncthreads();

        // GEMM-1: S[4][8] = Q(64x64) . K^T(64x128), contraction over d
        float S[4][8];
        #pragma unroll
        for (int i = 0; i < 4; i++)
            #pragma unroll
            for (int j = 0; j < 8; j++) S[i][j] = 0.f;
        #pragma unroll 4
        for (int kk = 0; kk < 64; kk++) {
            float a[4], b[8];
            *(float4*)&a[0] = *(const float4*)&As[kk * 64 + tr * 4];
            *(float4*)&b[0] = *(const float4*)&sB[kk * 128 + tc * 8];
            *(float4*)&b[4] = *(const float4*)&sB[kk * 128 + tc * 8 + 4];
            #pragma unroll
            for (int i = 0; i < 4; i++)
                #pragma unroll
                for (int j = 0; j < 8; j++)
                    S[i][j] = fmaf(a[i], b[j], S[i][j]);
        }

        // Online softmax update (rows shared by 16 contiguous lanes)
        float f_i[4];
        #pragma unroll
        for (int i = 0; i < 4; i++) {
            float mx = -1e30f;
            #pragma unroll
            for (int j = 0; j < 8; j++) {
                S[i][j] *= 0.125f;              // 1/sqrt(64)
                mx = fmaxf(mx, S[i][j]);
            }
            #pragma unroll
            for (int o = 8; o > 0; o >>= 1)
                mx = fmaxf(mx, __shfl_xor_sync(0xffffffffu, mx, o));
            float mnew = fmaxf(m_i[i], mx);
            f_i[i] = __expf(m_i[i] - mnew);
            m_i[i] = mnew;
            float ssum = 0.f;
            #pragma unroll
            for (int j = 0; j < 8; j++) {
                S[i][j] = __expf(S[i][j] - mnew);
                ssum += S[i][j];
            }
            #pragma unroll
            for (int o = 8; o > 0; o >>= 1)
                ssum += __shfl_xor_sync(0xffffffffu, ssum, o);
            s_i[i] = s_i[i] * f_i[i] + ssum;
        }

        // Write P to smem k-major: Ps[key][query]
        #pragma unroll
        for (int j = 0; j < 8; j++)
            #pragma unroll
            for (int i = 0; i < 4; i++)
                Ps[(tc * 8 + j) * 64 + tr * 4 + i] = S[i][j];
        __syncthreads();  // GEMM-1 reads of sB done; Ps fully written

        // Stage V chunk row-major into sB: sB[key][d]
        for (int i = tid; i < 128 * 16; i += 256) {
            int r = i >> 4;
            int c = (i & 15) << 2;
            *(float4*)&sB[r * 64 + c] = *(const float4*)(Vb + (long)(c0 + r) * HD + c);
        }
        // Rescale running O by f while staging (register-only)
        #pragma unroll
        for (int i = 0; i < 4; i++)
            #pragma unroll
            for (int j = 0; j < 4; j++) acc2[i][j] *= f_i[i];
        __syncthreads();

        // GEMM-2: acc2(64x64) += P(64x128) . V(128x64), contraction over keys
        #pragma unroll 4
        for (int kk = 0; kk < 128; kk++) {
            float a[4], b[4];
            *(float4*)&a[0] = *(const float4*)&Ps[kk * 64 + tr * 4];
            *(float4*)&b[0] = *(const float4*)&sB[kk * 64 + tc * 4];
            #pragma unroll
            for (int i = 0; i < 4; i++)
                #pragma unroll
                for (int j = 0; j < 4; j++)
                    acc2[i][j] = fmaf(a[i], b[j], acc2[i][j]);
        }
    }

    // Epilogue: divide by softmax sum, write AO[q][h*64+d]
    #pragma unroll
    for (int i = 0; i < 4; i++) {
        float inv = 1.f / s_i[i];
        #pragma unroll
        for (int j = 0; j < 4; j++)
            AO[(long)(q0 + tr * 4 + i) * CD + h * HD + tc * 4 + j] = acc2[i][j] * inv;
    }
}

// ---------------------------------------------------------------------------
// Launch
// ---------------------------------------------------------------------------
extern "C" void kernel_launch(void* const* d_in, const int* in_sizes, int n_in,
                              void* d_out, int out_size)
{
    (void)in_sizes; (void)n_in; (void)out_size;
    const float* q  = (const float*)d_in[0];
    const float* k  = (const float*)d_in[1];
    const float* v  = (const float*)d_in[2];
    const float* Wq = (const float*)d_in[3];
    const float* bq = (const float*)d_in[4];
    const float* Wk = (const float*)d_in[5];
    const float* bk = (const float*)d_in[6];
    const float* Wv = (const float*)d_in[7];
    const float* bv = (const float*)d_in[8];
    const float* Wo = (const float*)d_in[9];
    const float* bo = (const float*)d_in[10];
    float* out = (float*)d_out;

    float *Qp, *Kg, *Vg, *AO;
    cudaGetSymbolAddress((void**)&Qp, g_Qp);
    cudaGetSymbolAddress((void**)&Kg, g_Kg);
    cudaGetSymbolAddress((void**)&Vg, g_Vg);
    cudaGetSymbolAddress((void**)&AO, g_AO);

    static bool attr_set = false;
    if (!attr_set) {
        cudaFuncSetAttribute(attn_fused, cudaFuncAttributeMaxDynamicSharedMemorySize,
                             80 * 1024);
        attr_set = true;
    }

    dim3 blk(256);

    // 1) Q projection: Qp = q @ Wq^T + bq               (1024 x 1024 x 1024)
    gemm_nt<64, 64, 8, 4, 4><<<dim3(CD / 64, TQN / 64, 1), blk>>>(
        q, CD, 0, 1, Wq, CD, 0, bq, 0, 1.0f, Qp, CD, 0, CD);

    // 2) K gather-projection: Kg[h][j][d] = k[h+16j,:] . Wk[h*64+d,:] + bk
    gemm_nt<64, 64, 8, 4, 4><<<dim3(1, NKEY / 64, NH), blk>>>(
        k, CD, (long)CD, 16, Wk, CD, (long)HD * CD, bk, HD, 1.0f,
        Kg, HD, (long)NKEY * HD, CD);

    // 3) V gather-projection: Vg[h][j][d] = v[h+16j,:] . Wv[h*64+d,:] + bv
    gemm_nt<64, 64, 8, 4, 4><<<dim3(1, NKEY / 64, NH), blk>>>(
        v, CD, (long)CD, 16, Wv, CD, (long)HD * CD, bv, HD, 1.0f,
        Vg, HD, (long)NKEY * HD, CD);

    // 4) Fused scores + softmax + AV
    attn_fused<<<dim3(TQN / 64, NH), blk, 80 * 1024>>>(Qp, Kg, Vg, AO);

    // 5) Output projection: out = AO @ Wo^T + bo        (1024 x 1024 x 1024)
    gemm_nt<64, 64, 8, 4, 4><<<dim3(CD / 64, TQN / 64, 1), blk>>>(
        AO, CD, 0, 1, Wo, CD, 0, bo, 0, 1.0f, out, CD, 0, CD);
}

// round 6
// speedup vs baseline: 1.9380x; 1.9380x over previous
#include <cuda_runtime.h>
#include <cstdint>

// Problem constants
#define CD    1024   // d_model
#define TQN   1024   // query tokens
#define NH    16     // heads
#define HD    64     // head dim
#define NKEY  512    // keys per head after HEPOS gather (8192/16)

// ---------------------------------------------------------------------------
// Scratch (device globals; runtime allocation is forbidden)
// ---------------------------------------------------------------------------
__device__ __align__(256) float g_Qp[TQN * CD];          // Q projection
__device__ __align__(256) float g_Kg[NH * NKEY * HD];    // gathered/projected K [h][j][d]
__device__ __align__(256) float g_Vg[NH * NKEY * HD];    // gathered/projected V [h][j][d]
__device__ __align__(256) float g_AO[TQN * CD];          // attention output

// ---------------------------------------------------------------------------
// mma.sync helpers (legacy tensor-core path — valid on base sm_100 target)
// ---------------------------------------------------------------------------
__device__ __forceinline__ uint32_t f2tf(float x) {
    uint32_t u;
    asm("cvt.rna.tf32.f32 %0, %1;" : "=r"(u) : "f"(x));
    return u;
}
// D(16x8,f32) += A(16x8,tf32) * B(8x8,tf32)
__device__ __forceinline__ void mma8(float* c, const uint32_t* a, const uint32_t* b) {
    asm volatile(
        "mma.sync.aligned.m16n8k8.row.col.f32.tf32.tf32.f32 "
        "{%0,%1,%2,%3}, {%4,%5,%6,%7}, {%8,%9}, {%0,%1,%2,%3};\n"
        : "+f"(c[0]), "+f"(c[1]), "+f"(c[2]), "+f"(c[3])
        : "r"(a[0]), "r"(a[1]), "r"(a[2]), "r"(a[3]), "r"(b[0]), "r"(b[1]));
}

// ---------------------------------------------------------------------------
// Projection GEMM (tf32 mma): C[m,n] = sum_k A[m*rowMul, k] * B[n, k] + bias[n]
// BM=128, BN=64, BK=32. 256 threads = 8 warps in a 4(M) x 2(N) grid;
// warp tile 32x64? no: 32 rows x 32 cols (2 m-tiles x 4 n-tiles of m16n8).
// Smem stride 36 floats -> fragment loads provably bank-conflict-free.
// ---------------------------------------------------------------------------
__global__ __launch_bounds__(256)
void gemm_mma(const float* __restrict__ A, int lda, long aZ, int rowMul,
              const float* __restrict__ B, int ldb, long bZ,
              const float* __restrict__ bias, int biasZ,
              float* __restrict__ C, int ldc, long cZ, int K)
{
    __shared__ uint32_t As[128 * 36];
    __shared__ uint32_t Bs[64 * 36];

    const int tid  = threadIdx.x;
    const int wid  = tid >> 5;
    const int lane = tid & 31;
    const int g    = lane >> 2;       // 0..7
    const int tc   = lane & 3;        // 0..3
    const int wm   = wid & 3;         // 0..3 (M)
    const int wn   = wid >> 2;        // 0..1 (N)

    const int z  = blockIdx.z;
    const int m0 = blockIdx.y * 128;
    const int n0 = blockIdx.x * 64;

    const float* Ab = A + (long)z * aZ;
    const float* Bb = B + (long)z * bZ + (long)n0 * ldb;
    const float* biasb = bias + (long)z * biasZ + n0;
    float* Cb = C + (long)z * cZ;

    float acc[2][4][4];
    #pragma unroll
    for (int mt = 0; mt < 2; mt++)
        #pragma unroll
        for (int nt = 0; nt < 4; nt++)
            #pragma unroll
            for (int i = 0; i < 4; i++) acc[mt][nt][i] = 0.f;

    for (int k0 = 0; k0 < K; k0 += 32) {
        __syncthreads();
        // Stage A (128 x 32) as tf32
        #pragma unroll
        for (int i = tid; i < 128 * 8; i += 256) {
            int r = i >> 3, cc = (i & 7) << 2;
            float4 t = *(const float4*)(Ab + (long)(m0 + r) * rowMul * lda + k0 + cc);
            uint32_t* d = &As[r * 36 + cc];
            d[0] = f2tf(t.x); d[1] = f2tf(t.y); d[2] = f2tf(t.z); d[3] = f2tf(t.w);
        }
        // Stage B (64 x 32) as tf32
        #pragma unroll
        for (int i = tid; i < 64 * 8; i += 256) {
            int r = i >> 3, cc = (i & 7) << 2;
            float4 t = *(const float4*)(Bb + (long)r * ldb + k0 + cc);
            uint32_t* d = &Bs[r * 36 + cc];
            d[0] = f2tf(t.x); d[1] = f2tf(t.y); d[2] = f2tf(t.z); d[3] = f2tf(t.w);
        }
        __syncthreads();

        #pragma unroll
        for (int ks = 0; ks < 4; ks++) {
            const int kb = ks * 8;
            uint32_t a[2][4], b[4][2];
            #pragma unroll
            for (int mt = 0; mt < 2; mt++) {
                int row = wm * 32 + mt * 16;
                a[mt][0] = As[(row + g) * 36 + kb + tc];
                a[mt][1] = As[(row + 8 + g) * 36 + kb + tc];
                a[mt][2] = As[(row + g) * 36 + kb + tc + 4];
                a[mt][3] = As[(row + 8 + g) * 36 + kb + tc + 4];
            }
            #pragma unroll
            for (int nt = 0; nt < 4; nt++) {
                int col = wn * 32 + nt * 8;
                b[nt][0] = Bs[(col + g) * 36 + kb + tc];
                b[nt][1] = Bs[(col + g) * 36 + kb + tc + 4];
            }
            #pragma unroll
            for (int mt = 0; mt < 2; mt++)
                #pragma unroll
                for (int nt = 0; nt < 4; nt++)
                    mma8(acc[mt][nt], a[mt], b[nt]);
        }
    }

    // Epilogue: bias + float2 stores (C frag cols 2tc, 2tc+1 are adjacent)
    #pragma unroll
    for (int mt = 0; mt < 2; mt++) {
        #pragma unroll
        for (int nt = 0; nt < 4; nt++) {
            int lrow = wm * 32 + mt * 16 + g;
            int lcol = wn * 32 + nt * 8 + 2 * tc;
            float bx = biasb[lcol], by = biasb[lcol + 1];
            float2 v0 = { acc[mt][nt][0] + bx, acc[mt][nt][1] + by };
            float2 v1 = { acc[mt][nt][2] + bx, acc[mt][nt][3] + by };
            *(float2*)(Cb + (long)(m0 + lrow) * ldc + n0 + lcol) = v0;
            *(float2*)(Cb + (long)(m0 + lrow + 8) * ldc + n0 + lcol) = v1;
        }
    }
}

// ---------------------------------------------------------------------------
// Fused attention (tf32 mma): per (head, 64-query tile).
// 128 threads = 4 warps; each warp owns 16 query rows. Q fragments live in
// registers for the whole kernel. 8 key chunks of 64:
//   S = 0.125 * Q.K^T (mma) -> online softmax (quad shfl) -> P to smem ->
//   O = f*O + P.V (mma), V staged TRANSPOSED so both B-fragment orientations
//   hit the conflict-free (g*4+tc) bank pattern at stride 68.
// ---------------------------------------------------------------------------
__global__ __launch_bounds__(128)
void attn_mma(const float* __restrict__ Qp, const float* __restrict__ Kg,
              const float* __restrict__ Vg, float* __restrict__ AO)
{
    __shared__ uint32_t KVs[64 * 68];   // K as [key][d], then V^T as [d][key]
    __shared__ uint32_t Ps[64 * 68];    // P as [q][key]

    const int h   = blockIdx.y;
    const int q0  = blockIdx.x * 64;
    const int tid = threadIdx.x;
    const int wid = tid >> 5;
    const int lane = tid & 31;
    const int g  = lane >> 2;
    const int tc = lane & 3;

    const float* Qb = Qp + (long)(q0 + wid * 16) * CD + h * HD;
    const float* Kb = Kg + (long)h * NKEY * HD;
    const float* Vb = Vg + (long)h * NKEY * HD;

    // Q fragments in registers: qa[kstep][4], kstep over d (64 = 8 x 8)
    uint32_t qa[8][4];
    #pragma unroll
    for (int ks = 0; ks < 8; ks++) {
        qa[ks][0] = f2tf(Qb[(long)g * CD + ks * 8 + tc]);
        qa[ks][1] = f2tf(Qb[(long)(g + 8) * CD + ks * 8 + tc]);
        qa[ks][2] = f2tf(Qb[(long)g * CD + ks * 8 + tc + 4]);
        qa[ks][3] = f2tf(Qb[(long)(g + 8) * CD + ks * 8 + tc + 4]);
    }

    float o[8][4];
    #pragma unroll
    for (int nt = 0; nt < 8; nt++)
        #pragma unroll
        for (int i = 0; i < 4; i++) o[nt][i] = 0.f;
    float m0_ = -1e30f, m1_ = -1e30f, s0 = 0.f, s1 = 0.f;

    for (int c0 = 0; c0 < NKEY; c0 += 64) {
        __syncthreads();   // prior chunk's PV fragment loads done
        // Stage K chunk [key][d], tf32
        #pragma unroll
        for (int i = tid; i < 64 * 16; i += 128) {
            int r = i >> 4, cc = (i & 15) << 2;
            float4 t = *(const float4*)(Kb + (long)(c0 + r) * HD + cc);
            uint32_t* d = &KVs[r * 68 + cc];
            d[0] = f2tf(t.x); d[1] = f2tf(t.y); d[2] = f2tf(t.z); d[3] = f2tf(t.w);
        }
        __syncthreads();

        // S = Q.K^T : warp computes 16q x 64key (8 n-tiles), K=64 (8 ksteps)
        float sc[8][4];
        #pragma unroll
        for (int nt = 0; nt < 8; nt++)
            #pragma unroll
            for (int i = 0; i < 4; i++) sc[nt][i] = 0.f;
        #pragma unroll
        for (int ks = 0; ks < 8; ks++) {
            #pragma unroll
            for (int nt = 0; nt < 8; nt++) {
                uint32_t b[2];
                b[0] = KVs[(nt * 8 + g) * 68 + ks * 8 + tc];
                b[1] = KVs[(nt * 8 + g) * 68 + ks * 8 + tc + 4];
                mma8(sc[nt], qa[ks], b);
            }
        }

        // Online softmax; rows r0 = wid*16+g (c0,c1), r1 = r0+8 (c2,c3).
        float mx0 = -1e30f, mx1 = -1e30f;
        #pragma unroll
        for (int nt = 0; nt < 8; nt++) {
            sc[nt][0] *= 0.125f; sc[nt][1] *= 0.125f;
            sc[nt][2] *= 0.125f; sc[nt][3] *= 0.125f;
            mx0 = fmaxf(mx0, fmaxf(sc[nt][0], sc[nt][1]));
            mx1 = fmaxf(mx1, fmaxf(sc[nt][2], sc[nt][3]));
        }
        mx0 = fmaxf(mx0, __shfl_xor_sync(0xffffffffu, mx0, 1));
        mx0 = fmaxf(mx0, __shfl_xor_sync(0xffffffffu, mx0, 2));
        mx1 = fmaxf(mx1, __shfl_xor_sync(0xffffffffu, mx1, 1));
        mx1 = fmaxf(mx1, __shfl_xor_sync(0xffffffffu, mx1, 2));
        float mn0 = fmaxf(m0_, mx0), mn1 = fmaxf(m1_, mx1);
        float f0 = __expf(m0_ - mn0), f1 = __expf(m1_ - mn1);
        m0_ = mn0; m1_ = mn1;
        float sum0 = 0.f, sum1 = 0.f;
        #pragma unroll
        for (int nt = 0; nt < 8; nt++) {
            sc[nt][0] = __expf(sc[nt][0] - mn0);
            sc[nt][1] = __expf(sc[nt][1] - mn0);
            sc[nt][2] = __expf(sc[nt][2] - mn1);
            sc[nt][3] = __expf(sc[nt][3] - mn1);
            sum0 += sc[nt][0] + sc[nt][1];
            sum1 += sc[nt][2] + sc[nt][3];
            // P -> smem [q][key] as tf32
            int col = nt * 8 + 2 * tc;
            Ps[(wid * 16 + g) * 68 + col]     = f2tf(sc[nt][0]);
            Ps[(wid * 16 + g) * 68 + col + 1] = f2tf(sc[nt][1]);
            Ps[(wid * 16 + 8 + g) * 68 + col]     = f2tf(sc[nt][2]);
            Ps[(wid * 16 + 8 + g) * 68 + col + 1] = f2tf(sc[nt][3]);
        }
        sum0 += __shfl_xor_sync(0xffffffffu, sum0, 1);
        sum0 += __shfl_xor_sync(0xffffffffu, sum0, 2);
        sum1 += __shfl_xor_sync(0xffffffffu, sum1, 1);
        sum1 += __shfl_xor_sync(0xffffffffu, sum1, 2);
        s0 = s0 * f0 + sum0;
        s1 = s1 * f1 + sum1;
        __syncthreads();   // Ps written; S-phase KVs reads done

        // Stage V chunk TRANSPOSED: V^T[d][key]
        #pragma unroll
        for (int i = tid; i < 64 * 16; i += 128) {
            int r = i >> 4, cc = (i & 15) << 2;    // r = key, cc = d
            float4 t = *(const float4*)(Vb + (long)(c0 + r) * HD + cc);
            KVs[(cc + 0) * 68 + r] = f2tf(t.x);
            KVs[(cc + 1) * 68 + r] = f2tf(t.y);
            KVs[(cc + 2) * 68 + r] = f2tf(t.z);
            KVs[(cc + 3) * 68 + r] = f2tf(t.w);
        }
        // Rescale running O while staging
        #pragma unroll
        for (int nt = 0; nt < 8; nt++) {
            o[nt][0] *= f0; o[nt][1] *= f0;
            o[nt][2] *= f1; o[nt][3] *= f1;
        }
        __syncthreads();

        // O += P.V : contraction over 64 keys (8 ksteps), n = d (8 n-tiles)
        #pragma unroll
        for (int ks = 0; ks < 8; ks++) {
            uint32_t pa[4];
            pa[0] = Ps[(wid * 16 + g) * 68 + ks * 8 + tc];
            pa[1] = Ps[(wid * 16 + 8 + g) * 68 + ks * 8 + tc];
            pa[2] = Ps[(wid * 16 + g) * 68 + ks * 8 + tc + 4];
            pa[3] = Ps[(wid * 16 + 8 + g) * 68 + ks * 8 + tc + 4];
            #pragma unroll
            for (int nt = 0; nt < 8; nt++) {
                uint32_t b[2];
                b[0] = KVs[(nt * 8 + g) * 68 + ks * 8 + tc];       // V^T[d][key]
                b[1] = KVs[(nt * 8 + g) * 68 + ks * 8 + tc + 4];
                mma8(o[nt], pa, b);
            }
        }
    }

    // Epilogue: normalize and store (float2; frag cols adjacent)
    float inv0 = 1.f / s0, inv1 = 1.f / s1;
    #pragma unroll
    for (int nt = 0; nt < 8; nt++) {
        int row = q0 + wid * 16 + g;
        int col = h * HD + nt * 8 + 2 * tc;
        float2 v0 = { o[nt][0] * inv0, o[nt][1] * inv0 };
        float2 v1 = { o[nt][2] * inv1, o[nt][3] * inv1 };
        *(float2*)(AO + (long)row * CD + col) = v0;
        *(float2*)(AO + (long)(row + 8) * CD + col) = v1;
    }
}

// ---------------------------------------------------------------------------
// Launch
// ---------------------------------------------------------------------------
extern "C" void kernel_launch(void* const* d_in, const int* in_sizes, int n_in,
                              void* d_out, int out_size)
{
    (void)in_sizes; (void)n_in; (void)out_size;
    const float* q  = (const float*)d_in[0];
    const float* k  = (const float*)d_in[1];
    const float* v  = (const float*)d_in[2];
    const float* Wq = (const float*)d_in[3];
    const float* bq = (const float*)d_in[4];
    const float* Wk = (const float*)d_in[5];
    const float* bk = (const float*)d_in[6];
    const float* Wv = (const float*)d_in[7];
    const float* bv = (const float*)d_in[8];
    const float* Wo = (const float*)d_in[9];
    const float* bo = (const float*)d_in[10];
    float* out = (float*)d_out;

    float *Qp, *Kg, *Vg, *AO;
    cudaGetSymbolAddress((void**)&Qp, g_Qp);
    cudaGetSymbolAddress((void**)&Kg, g_Kg);
    cudaGetSymbolAddress((void**)&Vg, g_Vg);
    cudaGetSymbolAddress((void**)&AO, g_AO);

    dim3 blk(256);

    // 1) Q projection: Qp = q @ Wq^T + bq   (M=1024, N=1024, K=1024) — 128 blocks
    gemm_mma<<<dim3(CD / 64, TQN / 128, 1), blk>>>(
        q, CD, 0, 1, Wq, CD, 0, bq, 0, Qp, CD, 0, CD);

    // 2) K gather-projection: Kg[h][j][d] = k[h+16j,:] . Wk[h*64+d,:] + bk
    //    (M=512, N=64, K=1024) x 16 heads — 64 blocks
    gemm_mma<<<dim3(1, NKEY / 128, NH), blk>>>(
        k, CD, (long)CD, 16, Wk, CD, (long)HD * CD, bk, HD,
        Kg, HD, (long)NKEY * HD, CD);

    // 3) V gather-projection: Vg[h][j][d] = v[h+16j,:] . Wv[h*64+d,:] + bv
    gemm_mma<<<dim3(1, NKEY / 128, NH), blk>>>(
        v, CD, (long)CD, 16, Wv, CD, (long)HD * CD, bv, HD,
        Vg, HD, (long)NKEY * HD, CD);

    // 4) Fused scores + softmax + AV (tf32 mma) — 256 blocks x 128 threads
    attn_mma<<<dim3(TQN / 64, NH), dim3(128)>>>(Qp, Kg, Vg, AO);

    // 5) Output projection: out = AO @ Wo^T + bo  (M=1024, N=1024, K=1024)
    gemm_mma<<<dim3(CD / 64, TQN / 128, 1), blk>>>(
        AO, CD, 0, 1, Wo, CD, 0, bo, 0, out, CD, 0, CD);
}

// round 7
// speedup vs baseline: 3.6175x; 1.8666x over previous
#include <cuda_runtime.h>
#include <cstdint>

// Problem constants
#define CD    1024   // d_model
#define TQN   1024   // query tokens
#define NH    16     // heads
#define HD    64     // head dim
#define NKEY  512    // keys per head after HEPOS gather (8192/16)

// ---------------------------------------------------------------------------
// Scratch (device globals; runtime allocation is forbidden)
// ---------------------------------------------------------------------------
__device__ __align__(256) float g_Qp[TQN * CD];          // Q projection
__device__ __align__(256) float g_Kg[NH * NKEY * HD];    // gathered/projected K [h][j][d]
__device__ __align__(256) float g_Vg[NH * NKEY * HD];    // gathered/projected V [h][j][d]
__device__ __align__(256) float g_AO[TQN * CD];          // attention output

// ---------------------------------------------------------------------------
// mma.sync helpers (legacy tensor-core path — valid on base sm_100 target)
// ---------------------------------------------------------------------------
__device__ __forceinline__ uint32_t f2tf(float x) {
    uint32_t u;
    asm("cvt.rna.tf32.f32 %0, %1;" : "=r"(u) : "f"(x));
    return u;
}
// D(16x8,f32) += A(16x8,tf32) * B(8x8,tf32)
__device__ __forceinline__ void mma8(float* c, const uint32_t* a, const uint32_t* b) {
    asm volatile(
        "mma.sync.aligned.m16n8k8.row.col.f32.tf32.tf32.f32 "
        "{%0,%1,%2,%3}, {%4,%5,%6,%7}, {%8,%9}, {%0,%1,%2,%3};\n"
        : "+f"(c[0]), "+f"(c[1]), "+f"(c[2]), "+f"(c[3])
        : "r"(a[0]), "r"(a[1]), "r"(a[2]), "r"(a[3]), "r"(b[0]), "r"(b[1]));
}

// ---------------------------------------------------------------------------
// Projection GEMM (tf32 mma): C[m,n] = sum_k A[m*rowMul, k] * B[n, k] + bias[n]
// BM=128, BN=64, BK=64. 256 threads = 8 warps (4M x 2N), warp tile 32x32.
// Software pipeline: LDG chunk i+1 into registers while HMMAs run on chunk i.
// Smem stride 68 (68 mod 32 = 4 -> fragment loads conflict-free).
// Dynamic smem: As 128*68*4 + Bs 64*68*4 = 52224 B.
// ---------------------------------------------------------------------------
#define PSTRIDE 68
#define GSM_BYTES ((128 * PSTRIDE + 64 * PSTRIDE) * 4)

__global__ __launch_bounds__(256)
void gemm_mma(const float* __restrict__ A, int lda, long aZ, int rowMul,
              const float* __restrict__ B, int ldb, long bZ,
              const float* __restrict__ bias, int biasZ,
              float* __restrict__ C, int ldc, long cZ, int K)
{
    extern __shared__ uint32_t gsm[];
    uint32_t* As = gsm;                   // [128][68]
    uint32_t* Bs = gsm + 128 * PSTRIDE;   // [64][68]

    const int tid  = threadIdx.x;
    const int wid  = tid >> 5;
    const int lane = tid & 31;
    const int g    = lane >> 2;       // 0..7
    const int tc   = lane & 3;        // 0..3
    const int wm   = wid & 3;         // 0..3 (M)
    const int wn   = wid >> 2;        // 0..1 (N)

    const int z  = blockIdx.z;
    const int m0 = blockIdx.y * 128;
    const int n0 = blockIdx.x * 64;

    const float* Ab = A + (long)z * aZ;
    const float* Bb = B + (long)z * bZ + (long)n0 * ldb;
    const float* biasb = bias + (long)z * biasZ + n0;
    float* Cb = C + (long)z * cZ;

    // Per-thread staging slices (BK=64): A 8 x float4, B 4 x float4
    // index i = tid + it*256 ; r = i>>4 ; cc = (i&15)*4
    float4 areg[8], breg[4];

    auto ldg_chunk = [&](int k0) {
        #pragma unroll
        for (int it = 0; it < 8; it++) {
            int i = tid + it * 256;
            int r = i >> 4, cc = (i & 15) << 2;
            areg[it] = *(const float4*)(Ab + (long)(m0 + r) * rowMul * lda + k0 + cc);
        }
        #pragma unroll
        for (int it = 0; it < 4; it++) {
            int i = tid + it * 256;
            int r = i >> 4, cc = (i & 15) << 2;
            breg[it] = *(const float4*)(Bb + (long)r * ldb + k0 + cc);
        }
    };
    auto sts_chunk = [&]() {
        #pragma unroll
        for (int it = 0; it < 8; it++) {
            int i = tid + it * 256;
            int r = i >> 4, cc = (i & 15) << 2;
            uint32_t* d = &As[r * PSTRIDE + cc];
            d[0] = f2tf(areg[it].x); d[1] = f2tf(areg[it].y);
            d[2] = f2tf(areg[it].z); d[3] = f2tf(areg[it].w);
        }
        #pragma unroll
        for (int it = 0; it < 4; it++) {
            int i = tid + it * 256;
            int r = i >> 4, cc = (i & 15) << 2;
            uint32_t* d = &Bs[r * PSTRIDE + cc];
            d[0] = f2tf(breg[it].x); d[1] = f2tf(breg[it].y);
            d[2] = f2tf(breg[it].z); d[3] = f2tf(breg[it].w);
        }
    };

    float acc[2][4][4];
    #pragma unroll
    for (int mt = 0; mt < 2; mt++)
        #pragma unroll
        for (int nt = 0; nt < 4; nt++)
            #pragma unroll
            for (int i = 0; i < 4; i++) acc[mt][nt][i] = 0.f;

    const int NCH = K / 64;
    ldg_chunk(0);

    for (int ch = 0; ch < NCH; ch++) {
        __syncthreads();            // previous compute done reading smem
        sts_chunk();
        __syncthreads();            // staging visible
        if (ch + 1 < NCH) ldg_chunk((ch + 1) * 64);   // hidden behind HMMAs

        #pragma unroll
        for (int ks = 0; ks < 8; ks++) {
            const int kb = ks * 8;
            uint32_t a[2][4], b[4][2];
            #pragma unroll
            for (int mt = 0; mt < 2; mt++) {
                int row = wm * 32 + mt * 16;
                a[mt][0] = As[(row + g) * PSTRIDE + kb + tc];
                a[mt][1] = As[(row + 8 + g) * PSTRIDE + kb + tc];
                a[mt][2] = As[(row + g) * PSTRIDE + kb + tc + 4];
                a[mt][3] = As[(row + 8 + g) * PSTRIDE + kb + tc + 4];
            }
            #pragma unroll
            for (int nt = 0; nt < 4; nt++) {
                int col = wn * 32 + nt * 8;
                b[nt][0] = Bs[(col + g) * PSTRIDE + kb + tc];
                b[nt][1] = Bs[(col + g) * PSTRIDE + kb + tc + 4];
            }
            #pragma unroll
            for (int mt = 0; mt < 2; mt++)
                #pragma unroll
                for (int nt = 0; nt < 4; nt++)
                    mma8(acc[mt][nt], a[mt], b[nt]);
        }
    }

    // Epilogue: bias + float2 stores
    #pragma unroll
    for (int mt = 0; mt < 2; mt++) {
        #pragma unroll
        for (int nt = 0; nt < 4; nt++) {
            int lrow = wm * 32 + mt * 16 + g;
            int lcol = wn * 32 + nt * 8 + 2 * tc;
            float bx = biasb[lcol], by = biasb[lcol + 1];
            float2 v0 = { acc[mt][nt][0] + bx, acc[mt][nt][1] + by };
            float2 v1 = { acc[mt][nt][2] + bx, acc[mt][nt][3] + by };
            *(float2*)(Cb + (long)(m0 + lrow) * ldc + n0 + lcol) = v0;
            *(float2*)(Cb + (long)(m0 + lrow + 8) * ldc + n0 + lcol) = v1;
        }
    }
}

// ---------------------------------------------------------------------------
// Fused attention (tf32 mma): per (head, 64-query tile), 4 warps.
// Software pipeline: V_i LDG issued before S-phase mma, K_{i+1} LDG issued
// before PV-phase mma — all global latency hidden behind tensor work.
// ---------------------------------------------------------------------------
__global__ __launch_bounds__(128)
void attn_mma(const float* __restrict__ Qp, const float* __restrict__ Kg,
              const float* __restrict__ Vg, float* __restrict__ AO)
{
    __shared__ uint32_t KVs[64 * 68];   // K as [key][d], then V^T as [d][key]
    __shared__ uint32_t Ps[64 * 68];    // P as [q][key]

    const int h   = blockIdx.y;
    const int q0  = blockIdx.x * 64;
    const int tid = threadIdx.x;
    const int wid = tid >> 5;
    const int lane = tid & 31;
    const int g  = lane >> 2;
    const int tc = lane & 3;

    const float* Qb = Qp + (long)(q0 + wid * 16) * CD + h * HD;
    const float* Kb = Kg + (long)h * NKEY * HD;
    const float* Vb = Vg + (long)h * NKEY * HD;

    // Q fragments in registers for the whole kernel
    uint32_t qa[8][4];
    #pragma unroll
    for (int ks = 0; ks < 8; ks++) {
        qa[ks][0] = f2tf(Qb[(long)g * CD + ks * 8 + tc]);
        qa[ks][1] = f2tf(Qb[(long)(g + 8) * CD + ks * 8 + tc]);
        qa[ks][2] = f2tf(Qb[(long)g * CD + ks * 8 + tc + 4]);
        qa[ks][3] = f2tf(Qb[(long)(g + 8) * CD + ks * 8 + tc + 4]);
    }

    float o[8][4];
    #pragma unroll
    for (int nt = 0; nt < 8; nt++)
        #pragma unroll
        for (int i = 0; i < 4; i++) o[nt][i] = 0.f;
    float m0_ = -1e30f, m1_ = -1e30f, s0 = 0.f, s1 = 0.f;

    // Per-thread chunk slice: 8 x float4 (i = tid + it*128, r = i>>4, cc = (i&15)*4)
    float4 kreg[8], vreg[8];
    #pragma unroll
    for (int it = 0; it < 8; it++) {           // prefetch K_0
        int i = tid + it * 128;
        int r = i >> 4, cc = (i & 15) << 2;
        kreg[it] = *(const float4*)(Kb + (long)r * HD + cc);
    }

    for (int c0 = 0; c0 < NKEY; c0 += 64) {
        __syncthreads();   // prev chunk's PV reads of KVs/Ps complete
        // Stage K_i from registers
        #pragma unroll
        for (int it = 0; it < 8; it++) {
            int i = tid + it * 128;
            int r = i >> 4, cc = (i & 15) << 2;
            uint32_t* d = &KVs[r * 68 + cc];
            d[0] = f2tf(kreg[it].x); d[1] = f2tf(kreg[it].y);
            d[2] = f2tf(kreg[it].z); d[3] = f2tf(kreg[it].w);
        }
        // Prefetch V_i (lands during S-mma)
        #pragma unroll
        for (int it = 0; it < 8; it++) {
            int i = tid + it * 128;
            int r = i >> 4, cc = (i & 15) << 2;
            vreg[it] = *(const float4*)(Vb + (long)(c0 + r) * HD + cc);
        }
        __syncthreads();

        // S = Q.K^T : 16q x 64key per warp
        float sc[8][4];
        #pragma unroll
        for (int nt = 0; nt < 8; nt++)
            #pragma unroll
            for (int i = 0; i < 4; i++) sc[nt][i] = 0.f;
        #pragma unroll
        for (int ks = 0; ks < 8; ks++) {
            #pragma unroll
            for (int nt = 0; nt < 8; nt++) {
                uint32_t b[2];
                b[0] = KVs[(nt * 8 + g) * 68 + ks * 8 + tc];
                b[1] = KVs[(nt * 8 + g) * 68 + ks * 8 + tc + 4];
                mma8(sc[nt], qa[ks], b);
            }
        }

        // Online softmax (rows r0 = wid*16+g -> c0/c1, r1 = r0+8 -> c2/c3)
        float mx0 = -1e30f, mx1 = -1e30f;
        #pragma unroll
        for (int nt = 0; nt < 8; nt++) {
            sc[nt][0] *= 0.125f; sc[nt][1] *= 0.125f;
            sc[nt][2] *= 0.125f; sc[nt][3] *= 0.125f;
            mx0 = fmaxf(mx0, fmaxf(sc[nt][0], sc[nt][1]));
            mx1 = fmaxf(mx1, fmaxf(sc[nt][2], sc[nt][3]));
        }
        mx0 = fmaxf(mx0, __shfl_xor_sync(0xffffffffu, mx0, 1));
        mx0 = fmaxf(mx0, __shfl_xor_sync(0xffffffffu, mx0, 2));
        mx1 = fmaxf(mx1, __shfl_xor_sync(0xffffffffu, mx1, 1));
        mx1 = fmaxf(mx1, __shfl_xor_sync(0xffffffffu, mx1, 2));
        float mn0 = fmaxf(m0_, mx0), mn1 = fmaxf(m1_, mx1);
        float f0 = __expf(m0_ - mn0), f1 = __expf(m1_ - mn1);
        m0_ = mn0; m1_ = mn1;
        float sum0 = 0.f, sum1 = 0.f;
        #pragma unroll
        for (int nt = 0; nt < 8; nt++) {
            sc[nt][0] = __expf(sc[nt][0] - mn0);
            sc[nt][1] = __expf(sc[nt][1] - mn0);
            sc[nt][2] = __expf(sc[nt][2] - mn1);
            sc[nt][3] = __expf(sc[nt][3] - mn1);
            sum0 += sc[nt][0] + sc[nt][1];
            sum1 += sc[nt][2] + sc[nt][3];
            int col = nt * 8 + 2 * tc;
            Ps[(wid * 16 + g) * 68 + col]     = f2tf(sc[nt][0]);
            Ps[(wid * 16 + g) * 68 + col + 1] = f2tf(sc[nt][1]);
            Ps[(wid * 16 + 8 + g) * 68 + col]     = f2tf(sc[nt][2]);
            Ps[(wid * 16 + 8 + g) * 68 + col + 1] = f2tf(sc[nt][3]);
        }
        sum0 += __shfl_xor_sync(0xffffffffu, sum0, 1);
        sum0 += __shfl_xor_sync(0xffffffffu, sum0, 2);
        sum1 += __shfl_xor_sync(0xffffffffu, sum1, 1);
        sum1 += __shfl_xor_sync(0xffffffffu, sum1, 2);
        s0 = s0 * f0 + sum0;
        s1 = s1 * f1 + sum1;
        __syncthreads();   // Ps visible; S-phase KVs reads done

        // Stage V_i^T from registers: KVs[d][key]
        #pragma unroll
        for (int it = 0; it < 8; it++) {
            int i = tid + it * 128;
            int r = i >> 4, cc = (i & 15) << 2;   // r = key, cc = d
            KVs[(cc + 0) * 68 + r] = f2tf(vreg[it].x);
            KVs[(cc + 1) * 68 + r] = f2tf(vreg[it].y);
            KVs[(cc + 2) * 68 + r] = f2tf(vreg[it].z);
            KVs[(cc + 3) * 68 + r] = f2tf(vreg[it].w);
        }
        // Prefetch K_{i+1} (lands during PV-mma)
        if (c0 + 64 < NKEY) {
            #pragma unroll
            for (int it = 0; it < 8; it++) {
                int i = tid + it * 128;
                int r = i >> 4, cc = (i & 15) << 2;
                kreg[it] = *(const float4*)(Kb + (long)(c0 + 64 + r) * HD + cc);
            }
        }
        // Rescale running O
        #pragma unroll
        for (int nt = 0; nt < 8; nt++) {
            o[nt][0] *= f0; o[nt][1] *= f0;
            o[nt][2] *= f1; o[nt][3] *= f1;
        }
        __syncthreads();

        // O += P.V
        #pragma unroll
        for (int ks = 0; ks < 8; ks++) {
            uint32_t pa[4];
            pa[0] = Ps[(wid * 16 + g) * 68 + ks * 8 + tc];
            pa[1] = Ps[(wid * 16 + 8 + g) * 68 + ks * 8 + tc];
            pa[2] = Ps[(wid * 16 + g) * 68 + ks * 8 + tc + 4];
            pa[3] = Ps[(wid * 16 + 8 + g) * 68 + ks * 8 + tc + 4];
            #pragma unroll
            for (int nt = 0; nt < 8; nt++) {
                uint32_t b[2];
                b[0] = KVs[(nt * 8 + g) * 68 + ks * 8 + tc];
                b[1] = KVs[(nt * 8 + g) * 68 + ks * 8 + tc + 4];
                mma8(o[nt], pa, b);
            }
        }
    }

    float inv0 = 1.f / s0, inv1 = 1.f / s1;
    #pragma unroll
    for (int nt = 0; nt < 8; nt++) {
        int row = q0 + wid * 16 + g;
        int col = h * HD + nt * 8 + 2 * tc;
        float2 v0 = { o[nt][0] * inv0, o[nt][1] * inv0 };
        float2 v1 = { o[nt][2] * inv1, o[nt][3] * inv1 };
        *(float2*)(AO + (long)row * CD + col) = v0;
        *(float2*)(AO + (long)(row + 8) * CD + col) = v1;
    }
}

// ---------------------------------------------------------------------------
// Launch
// ---------------------------------------------------------------------------
extern "C" void kernel_launch(void* const* d_in, const int* in_sizes, int n_in,
                              void* d_out, int out_size)
{
    (void)in_sizes; (void)n_in; (void)out_size;
    const float* q  = (const float*)d_in[0];
    const float* k  = (const float*)d_in[1];
    const float* v  = (const float*)d_in[2];
    const float* Wq = (const float*)d_in[3];
    const float* bq = (const float*)d_in[4];
    const float* Wk = (const float*)d_in[5];
    const float* bk = (const float*)d_in[6];
    const float* Wv = (const float*)d_in[7];
    const float* bv = (const float*)d_in[8];
    const float* Wo = (const float*)d_in[9];
    const float* bo = (const float*)d_in[10];
    float* out = (float*)d_out;

    float *Qp, *Kg, *Vg, *AO;
    cudaGetSymbolAddress((void**)&Qp, g_Qp);
    cudaGetSymbolAddress((void**)&Kg, g_Kg);
    cudaGetSymbolAddress((void**)&Vg, g_Vg);
    cudaGetSymbolAddress((void**)&AO, g_AO);

    cudaFuncSetAttribute(gemm_mma, cudaFuncAttributeMaxDynamicSharedMemorySize,
                         GSM_BYTES);

    dim3 blk(256);

    // 1) Q projection: Qp = q @ Wq^T + bq   (M=1024, N=1024, K=1024) — 128 blocks
    gemm_mma<<<dim3(CD / 64, TQN / 128, 1), blk, GSM_BYTES>>>(
        q, CD, 0, 1, Wq, CD, 0, bq, 0, Qp, CD, 0, CD);

    // 2) K gather-projection: Kg[h][j][d] = k[h+16j,:] . Wk[h*64+d,:] + bk
    gemm_mma<<<dim3(1, NKEY / 128, NH), blk, GSM_BYTES>>>(
        k, CD, (long)CD, 16, Wk, CD, (long)HD * CD, bk, HD,
        Kg, HD, (long)NKEY * HD, CD);

    // 3) V gather-projection: Vg[h][j][d] = v[h+16j,:] . Wv[h*64+d,:] + bv
    gemm_mma<<<dim3(1, NKEY / 128, NH), blk, GSM_BYTES>>>(
        v, CD, (long)CD, 16, Wv, CD, (long)HD * CD, bv, HD,
        Vg, HD, (long)NKEY * HD, CD);

    // 4) Fused scores + softmax + AV (tf32 mma) — 256 blocks x 128 threads
    attn_mma<<<dim3(TQN / 64, NH), dim3(128)>>>(Qp, Kg, Vg, AO);

    // 5) Output projection: out = AO @ Wo^T + bo
    gemm_mma<<<dim3(CD / 64, TQN / 128, 1), blk, GSM_BYTES>>>(
        AO, CD, 0, 1, Wo, CD, 0, bo, 0, out, CD, 0, CD);
}

// round 9
// speedup vs baseline: 4.0262x; 1.1130x over previous
#include <cuda_runtime.h>
#include <cstdint>

// Problem constants
#define CD    1024   // d_model
#define TQN   1024   // query tokens
#define NH    16     // heads
#define HD    64     // head dim
#define NKEY  512    // keys per head after HEPOS gather (8192/16)

// ---------------------------------------------------------------------------
// Scratch (device globals; runtime allocation is forbidden)
// ---------------------------------------------------------------------------
__device__ __align__(256) float g_Qp[TQN * CD];          // Q projection
__device__ __align__(256) float g_Kg[NH * NKEY * HD];    // gathered/projected K [h][j][d]
__device__ __align__(256) float g_Vg[NH * NKEY * HD];    // gathered/projected V [h][j][d]
__device__ __align__(256) float g_AO[TQN * CD];          // attention output

// ---------------------------------------------------------------------------
// mma.sync helpers (legacy tensor-core path — valid on base sm_100 target)
// ---------------------------------------------------------------------------
__device__ __forceinline__ uint32_t f2tf(float x) {
    uint32_t u;
    asm("cvt.rna.tf32.f32 %0, %1;" : "=r"(u) : "f"(x));
    return u;
}
__device__ __forceinline__ void mma8(float* c, const uint32_t* a, const uint32_t* b) {
    asm volatile(
        "mma.sync.aligned.m16n8k8.row.col.f32.tf32.tf32.f32 "
        "{%0,%1,%2,%3}, {%4,%5,%6,%7}, {%8,%9}, {%0,%1,%2,%3};\n"
        : "+f"(c[0]), "+f"(c[1]), "+f"(c[2]), "+f"(c[3])
        : "r"(a[0]), "r"(a[1]), "r"(a[2]), "r"(a[3]), "r"(b[0]), "r"(b[1]));
}

#define PSTRIDE 68
#define GSM_BYTES ((128 * PSTRIDE + 64 * PSTRIDE) * 4)   // 52224

// ---------------------------------------------------------------------------
// Shared GEMM core (tf32 mma): C[cm0+m, cn0+n] = sum_k A[(m0+m)*rowMul, k] *
// B[n, k] + bias[n].  BM=128, BN=64, BK=64, 256 threads = 8 warps (4M x 2N),
// register-prefetch software pipeline, padded smem stride 68 (conflict-free).
// ---------------------------------------------------------------------------
__device__ __forceinline__ void gemm_core(
    const float* __restrict__ Ab, int lda, int rowMul, int m0,
    const float* __restrict__ Bb, int ldb,
    const float* __restrict__ biasb,
    float* __restrict__ Cb, int ldc, int cm0, int cn0, int K,
    uint32_t* As, uint32_t* Bs)
{
    const int tid  = threadIdx.x;
    const int wid  = tid >> 5;
    const int lane = tid & 31;
    const int g    = lane >> 2;
    const int tc   = lane & 3;
    const int wm   = wid & 3;
    const int wn   = wid >> 2;

    float4 areg[8], breg[4];
    auto ldg_chunk = [&](int k0) {
        #pragma unroll
        for (int it = 0; it < 8; it++) {
            int i = tid + it * 256;
            int r = i >> 4, cc = (i & 15) << 2;
            areg[it] = *(const float4*)(Ab + (long)(m0 + r) * rowMul * lda + k0 + cc);
        }
        #pragma unroll
        for (int it = 0; it < 4; it++) {
            int i = tid + it * 256;
            int r = i >> 4, cc = (i & 15) << 2;
            breg[it] = *(const float4*)(Bb + (long)r * ldb + k0 + cc);
        }
    };
    auto sts_chunk = [&]() {
        #pragma unroll
        for (int it = 0; it < 8; it++) {
            int i = tid + it * 256;
            int r = i >> 4, cc = (i & 15) << 2;
            uint32_t* d = &As[r * PSTRIDE + cc];
            d[0] = f2tf(areg[it].x); d[1] = f2tf(areg[it].y);
            d[2] = f2tf(areg[it].z); d[3] = f2tf(areg[it].w);
        }
        #pragma unroll
        for (int it = 0; it < 4; it++) {
            int i = tid + it * 256;
            int r = i >> 4, cc = (i & 15) << 2;
            uint32_t* d = &Bs[r * PSTRIDE + cc];
            d[0] = f2tf(breg[it].x); d[1] = f2tf(breg[it].y);
            d[2] = f2tf(breg[it].z); d[3] = f2tf(breg[it].w);
        }
    };

    float acc[2][4][4];
    #pragma unroll
    for (int mt = 0; mt < 2; mt++)
        #pragma unroll
        for (int nt = 0; nt < 4; nt++)
            #pragma unroll
            for (int i = 0; i < 4; i++) acc[mt][nt][i] = 0.f;

    const int NCH = K / 64;
    ldg_chunk(0);

    for (int ch = 0; ch < NCH; ch++) {
        __syncthreads();
        sts_chunk();
        __syncthreads();
        if (ch + 1 < NCH) ldg_chunk((ch + 1) * 64);

        #pragma unroll
        for (int ks = 0; ks < 8; ks++) {
            const int kb = ks * 8;
            uint32_t a[2][4], b[4][2];
            #pragma unroll
            for (int mt = 0; mt < 2; mt++) {
                int row = wm * 32 + mt * 16;
                a[mt][0] = As[(row + g) * PSTRIDE + kb + tc];
                a[mt][1] = As[(row + 8 + g) * PSTRIDE + kb + tc];
                a[mt][2] = As[(row + g) * PSTRIDE + kb + tc + 4];
                a[mt][3] = As[(row + 8 + g) * PSTRIDE + kb + tc + 4];
            }
            #pragma unroll
            for (int nt = 0; nt < 4; nt++) {
                int col = wn * 32 + nt * 8;
                b[nt][0] = Bs[(col + g) * PSTRIDE + kb + tc];
                b[nt][1] = Bs[(col + g) * PSTRIDE + kb + tc + 4];
            }
            #pragma unroll
            for (int mt = 0; mt < 2; mt++)
                #pragma unroll
                for (int nt = 0; nt < 4; nt++)
                    mma8(acc[mt][nt], a[mt], b[nt]);
        }
    }

    #pragma unroll
    for (int mt = 0; mt < 2; mt++) {
        #pragma unroll
        for (int nt = 0; nt < 4; nt++) {
            int lrow = wm * 32 + mt * 16 + g;
            int lcol = wn * 32 + nt * 8 + 2 * tc;
            float bx = biasb[lcol], by = biasb[lcol + 1];
            float2 v0 = { acc[mt][nt][0] + bx, acc[mt][nt][1] + by };
            float2 v1 = { acc[mt][nt][2] + bx, acc[mt][nt][3] + by };
            *(float2*)(Cb + (long)(cm0 + lrow) * ldc + cn0 + lcol) = v0;
            *(float2*)(Cb + (long)(cm0 + lrow + 8) * ldc + cn0 + lcol) = v1;
        }
    }
}

// ---------------------------------------------------------------------------
// Merged Q+K+V projection: 256 blocks.
//   b in [0,128): Q  — m-tile b>>4, n-tile b&15      (M=1024, N=1024)
//   b in [128,192): K-gather — head (b-128)>>2, m-tile (b-128)&3 (M=512, N=64)
//   b in [192,256): V-gather — same layout
// ---------------------------------------------------------------------------
__global__ __launch_bounds__(256)
void qkv_mma(const float* __restrict__ q,  const float* __restrict__ Wq,
             const float* __restrict__ bq,
             const float* __restrict__ k,  const float* __restrict__ Wk,
             const float* __restrict__ bk,
             const float* __restrict__ v,  const float* __restrict__ Wv,
             const float* __restrict__ bv,
             float* __restrict__ Qp, float* __restrict__ Kg,
             float* __restrict__ Vg)
{
    extern __shared__ uint32_t gsm[];
    uint32_t* As = gsm;
    uint32_t* Bs = gsm + 128 * PSTRIDE;

    const int b = blockIdx.x;
    const float *Ab, *Bb, *biasb;
    float* Cb;
    int rowMul, m0, cn0, ldc;

    if (b < 128) {
        int mt = b >> 4, nt = b & 15;
        Ab = q;  rowMul = 1;  m0 = mt * 128;
        cn0 = nt * 64;
        Bb = Wq + (long)cn0 * CD;  biasb = bq + cn0;
        Cb = Qp; ldc = CD;
    } else if (b < 192) {
        int idx = b - 128, h = idx >> 2, mt = idx & 3;
        Ab = k + (long)h * CD;  rowMul = 16;  m0 = mt * 128;
        cn0 = 0;
        Bb = Wk + (long)h * HD * CD;  biasb = bk + h * HD;
        Cb = Kg + (long)h * NKEY * HD; ldc = HD;
    } else {
        int idx = b - 192, h = idx >> 2, mt = idx & 3;
        Ab = v + (long)h * CD;  rowMul = 16;  m0 = mt * 128;
        cn0 = 0;
        Bb = Wv + (long)h * HD * CD;  biasb = bv + h * HD;
        Cb = Vg + (long)h * NKEY * HD; ldc = HD;
    }

    gemm_core(Ab, CD, rowMul, m0, Bb, CD, biasb, Cb, ldc, m0, cn0, CD, As, Bs);
}

// ---------------------------------------------------------------------------
// Output projection (standalone): out = AO @ Wo^T + bo
// ---------------------------------------------------------------------------
__global__ __launch_bounds__(256)
void gemm_mma(const float* __restrict__ A,
              const float* __restrict__ B,
              const float* __restrict__ bias,
              float* __restrict__ C)
{
    extern __shared__ uint32_t gsm[];
    uint32_t* As = gsm;
    uint32_t* Bs = gsm + 128 * PSTRIDE;
    const int m0 = blockIdx.y * 128;
    const int n0 = blockIdx.x * 64;
    gemm_core(A, CD, 1, m0, B + (long)n0 * CD, CD, bias + n0,
              C, CD, m0, n0, CD, As, Bs);
}

// ---------------------------------------------------------------------------
// Fused attention, split-K: block = 32 queries x 1 head; 4 warps =
// 2 query-groups x 2 key-halves (256 keys each). Per-half K/V/P smem; 4 key
// chunks of 64 per half; flash-style (m,s,O) merge through smem at the end.
// Dynamic smem: KVs 2*64*68 + Ps 2*32*68 (uint32) = 52224 B.
// ---------------------------------------------------------------------------
__global__ __launch_bounds__(128)
void attn_mma(const float* __restrict__ Qp, const float* __restrict__ Kg,
              const float* __restrict__ Vg, float* __restrict__ AO)
{
    extern __shared__ uint32_t asm_[];
    uint32_t* KVs = asm_;                  // [2][64*68]
    uint32_t* Ps  = asm_ + 2 * 64 * 68;    // [2][32*68]

    const int h    = blockIdx.y;
    const int q0   = blockIdx.x * 32;
    const int tid  = threadIdx.x;
    const int wid  = tid >> 5;
    const int lane = tid & 31;
    const int g    = lane >> 2;
    const int tc   = lane & 3;
    const int qg   = wid & 1;       // query group (rows qg*16 .. qg*16+15)
    const int half = wid >> 1;      // key half (0: keys 0..255, 1: 256..511)
    const int s    = tid & 63;      // staging index within half (64 threads)

    uint32_t* KVh = KVs + half * 64 * 68;
    uint32_t* Psh = Ps  + half * 32 * 68;

    const float* Qb = Qp + (long)(q0 + qg * 16) * CD + h * HD;
    const float* Kb = Kg + (long)h * NKEY * HD + (long)half * 256 * HD;
    const float* Vb = Vg + (long)h * NKEY * HD + (long)half * 256 * HD;

    // Q fragments in registers (16 rows per warp)
    uint32_t qa[8][4];
    #pragma unroll
    for (int ks = 0; ks < 8; ks++) {
        qa[ks][0] = f2tf(Qb[(long)g * CD + ks * 8 + tc]);
        qa[ks][1] = f2tf(Qb[(long)(g + 8) * CD + ks * 8 + tc]);
        qa[ks][2] = f2tf(Qb[(long)g * CD + ks * 8 + tc + 4]);
        qa[ks][3] = f2tf(Qb[(long)(g + 8) * CD + ks * 8 + tc + 4]);
    }

    float o[8][4];
    #pragma unroll
    for (int nt = 0; nt < 8; nt++)
        #pragma unroll
        for (int i = 0; i < 4; i++) o[nt][i] = 0.f;
    float m0_ = -1e30f, m1_ = -1e30f, s0 = 0.f, s1 = 0.f;

    for (int it = 0; it < 4; it++) {       // 4 chunks of 64 keys per half
        const int c0 = it * 64;
        __syncthreads();
        // Stage K chunk [key][d] (the 2 warps of this half stage their buffer)
        for (int i = s; i < 64 * 16; i += 64) {
            int r = i >> 4, cc = (i & 15) << 2;
            float4 t = *(const float4*)(Kb + (long)(c0 + r) * HD + cc);
            uint32_t* d = &KVh[r * 68 + cc];
            d[0] = f2tf(t.x); d[1] = f2tf(t.y); d[2] = f2tf(t.z); d[3] = f2tf(t.w);
        }
        __syncthreads();

        // S = Q.K^T : 16q x 64key per warp
        float sc[8][4];
        #pragma unroll
        for (int nt = 0; nt < 8; nt++)
            #pragma unroll
            for (int i = 0; i < 4; i++) sc[nt][i] = 0.f;
        #pragma unroll
        for (int ks = 0; ks < 8; ks++) {
            #pragma unroll
            for (int nt = 0; nt < 8; nt++) {
                uint32_t b[2];
                b[0] = KVh[(nt * 8 + g) * 68 + ks * 8 + tc];
                b[1] = KVh[(nt * 8 + g) * 68 + ks * 8 + tc + 4];
                mma8(sc[nt], qa[ks], b);
            }
        }

        // Online softmax (rows r0 = qg*16+g -> c0/c1, r1 = r0+8 -> c2/c3)
        float mx0 = -1e30f, mx1 = -1e30f;
        #pragma unroll
        for (int nt = 0; nt < 8; nt++) {
            sc[nt][0] *= 0.125f; sc[nt][1] *= 0.125f;
            sc[nt][2] *= 0.125f; sc[nt][3] *= 0.125f;
            mx0 = fmaxf(mx0, fmaxf(sc[nt][0], sc[nt][1]));
            mx1 = fmaxf(mx1, fmaxf(sc[nt][2], sc[nt][3]));
        }
        mx0 = fmaxf(mx0, __shfl_xor_sync(0xffffffffu, mx0, 1));
        mx0 = fmaxf(mx0, __shfl_xor_sync(0xffffffffu, mx0, 2));
        mx1 = fmaxf(mx1, __shfl_xor_sync(0xffffffffu, mx1, 1));
        mx1 = fmaxf(mx1, __shfl_xor_sync(0xffffffffu, mx1, 2));
        float mn0 = fmaxf(m0_, mx0), mn1 = fmaxf(m1_, mx1);
        float f0 = __expf(m0_ - mn0), f1 = __expf(m1_ - mn1);
        m0_ = mn0; m1_ = mn1;
        float sum0 = 0.f, sum1 = 0.f;
        #pragma unroll
        for (int nt = 0; nt < 8; nt++) {
            sc[nt][0] = __expf(sc[nt][0] - mn0);
            sc[nt][1] = __expf(sc[nt][1] - mn0);
            sc[nt][2] = __expf(sc[nt][2] - mn1);
            sc[nt][3] = __expf(sc[nt][3] - mn1);
            sum0 += sc[nt][0] + sc[nt][1];
            sum1 += sc[nt][2] + sc[nt][3];
            int col = nt * 8 + 2 * tc;
            Psh[(qg * 16 + g) * 68 + col]     = f2tf(sc[nt][0]);
            Psh[(qg * 16 + g) * 68 + col + 1] = f2tf(sc[nt][1]);
            Psh[(qg * 16 + 8 + g) * 68 + col]     = f2tf(sc[nt][2]);
            Psh[(qg * 16 + 8 + g) * 68 + col + 1] = f2tf(sc[nt][3]);
        }
        sum0 += __shfl_xor_sync(0xffffffffu, sum0, 1);
        sum0 += __shfl_xor_sync(0xffffffffu, sum0, 2);
        sum1 += __shfl_xor_sync(0xffffffffu, sum1, 1);
        sum1 += __shfl_xor_sync(0xffffffffu, sum1, 2);
        s0 = s0 * f0 + sum0;
        s1 = s1 * f1 + sum1;
        __syncthreads();

        // Stage V chunk TRANSPOSED [d][key]
        for (int i = s; i < 64 * 16; i += 64) {
            int r = i >> 4, cc = (i & 15) << 2;    // r = key, cc = d
            float4 t = *(const float4*)(Vb + (long)(c0 + r) * HD + cc);
            KVh[(cc + 0) * 68 + r] = f2tf(t.x);
            KVh[(cc + 1) * 68 + r] = f2tf(t.y);
            KVh[(cc + 2) * 68 + r] = f2tf(t.z);
            KVh[(cc + 3) * 68 + r] = f2tf(t.w);
        }
        #pragma unroll
        for (int nt = 0; nt < 8; nt++) {
            o[nt][0] *= f0; o[nt][1] *= f0;
            o[nt][2] *= f1; o[nt][3] *= f1;
        }
        __syncthreads();

        // O += P.V
        #pragma unroll
        for (int ks = 0; ks < 8; ks++) {
            uint32_t pa[4];
            pa[0] = Psh[(qg * 16 + g) * 68 + ks * 8 + tc];
            pa[1] = Psh[(qg * 16 + 8 + g) * 68 + ks * 8 + tc];
            pa[2] = Psh[(qg * 16 + g) * 68 + ks * 8 + tc + 4];
            pa[3] = Psh[(qg * 16 + 8 + g) * 68 + ks * 8 + tc + 4];
            #pragma unroll
            for (int nt = 0; nt < 8; nt++) {
                uint32_t b[2];
                b[0] = KVh[(nt * 8 + g) * 68 + ks * 8 + tc];
                b[1] = KVh[(nt * 8 + g) * 68 + ks * 8 + tc + 4];
                mma8(o[nt], pa, b);
            }
        }
    }

    // ---- Merge key-halves (flash-decode style) ----
    __syncthreads();                       // all PV reads of Ps/KVs done
    float* Osm = (float*)Ps;               // [32][68] — half-1's unnormalized O
    float* MS  = (float*)(Ps + 32 * 68);   // [32][2]  — half-1's (m, s)

    const int row0 = qg * 16 + g;
    const int row1 = row0 + 8;

    if (half == 1) {
        if (tc == 0) {
            MS[row0 * 2] = m0_;  MS[row0 * 2 + 1] = s0;
            MS[row1 * 2] = m1_;  MS[row1 * 2 + 1] = s1;
        }
        #pragma unroll
        for (int nt = 0; nt < 8; nt++) {
            int col = nt * 8 + 2 * tc;
            Osm[row0 * 68 + col]     = o[nt][0];
            Osm[row0 * 68 + col + 1] = o[nt][1];
            Osm[row1 * 68 + col]     = o[nt][2];
            Osm[row1 * 68 + col + 1] = o[nt][3];
        }
    }
    __syncthreads();

    if (half == 0) {
        float mB0 = MS[row0 * 2], sB0 = MS[row0 * 2 + 1];
        float mB1 = MS[row1 * 2], sB1 = MS[row1 * 2 + 1];
        float mM0 = fmaxf(m0_, mB0), mM1 = fmaxf(m1_, mB1);
        float eA0 = __expf(m0_ - mM0), eB0 = __expf(mB0 - mM0);
        float eA1 = __expf(m1_ - mM1), eB1 = __expf(mB1 - mM1);
        float inv0 = 1.f / (s0 * eA0 + sB0 * eB0);
        float inv1 = 1.f / (s1 * eA1 + sB1 * eB1);
        #pragma unroll
        for (int nt = 0; nt < 8; nt++) {
            int col = nt * 8 + 2 * tc;
            float2 v0, v1;
            v0.x = (o[nt][0] * eA0 + Osm[row0 * 68 + col]     * eB0) * inv0;
            v0.y = (o[nt][1] * eA0 + Osm[row0 * 68 + col + 1] * eB0) * inv0;
            v1.x = (o[nt][2] * eA1 + Osm[row1 * 68 + col]     * eB1) * inv1;
            v1.y = (o[nt][3] * eA1 + Osm[row1 * 68 + col + 1] * eB1) * inv1;
            *(float2*)(AO + (long)(q0 + row0) * CD + h * HD + col) = v0;
            *(float2*)(AO + (long)(q0 + row1) * CD + h * HD + col) = v1;
        }
    }
}

#define ATT_SM_BYTES ((2 * 64 * 68 + 2 * 32 * 68) * 4)   // 52224

// ---------------------------------------------------------------------------
// Launch
// ---------------------------------------------------------------------------
extern "C" void kernel_launch(void* const* d_in, const int* in_sizes, int n_in,
                              void* d_out, int out_size)
{
    (void)in_sizes; (void)n_in; (void)out_size;
    const float* q  = (const float*)d_in[0];
    const float* k  = (const float*)d_in[1];
    const float* v  = (const float*)d_in[2];
    const float* Wq = (const float*)d_in[3];
    const float* bq = (const float*)d_in[4];
    const float* Wk = (const float*)d_in[5];
    const float* bk = (const float*)d_in[6];
    const float* Wv = (const float*)d_in[7];
    const float* bv = (const float*)d_in[8];
    const float* Wo = (const float*)d_in[9];
    const float* bo = (const float*)d_in[10];
    float* out = (float*)d_out;

    float *Qp, *Kg, *Vg, *AO;
    cudaGetSymbolAddress((void**)&Qp, g_Qp);
    cudaGetSymbolAddress((void**)&Kg, g_Kg);
    cudaGetSymbolAddress((void**)&Vg, g_Vg);
    cudaGetSymbolAddress((void**)&AO, g_AO);

    cudaFuncSetAttribute(qkv_mma,  cudaFuncAttributeMaxDynamicSharedMemorySize, GSM_BYTES);
    cudaFuncSetAttribute(gemm_mma, cudaFuncAttributeMaxDynamicSharedMemorySize, GSM_BYTES);
    cudaFuncSetAttribute(attn_mma, cudaFuncAttributeMaxDynamicSharedMemorySize, ATT_SM_BYTES);

    // 1) Merged Q + K-gather + V-gather projections — 256 blocks
    qkv_mma<<<256, 256, GSM_BYTES>>>(q, Wq, bq, k, Wk, bk, v, Wv, bv, Qp, Kg, Vg);

    // 2) Fused split-K attention — 512 blocks x 128 threads
    attn_mma<<<dim3(TQN / 32, NH), 128, ATT_SM_BYTES>>>(Qp, Kg, Vg, AO);

    // 3) Output projection — 128 blocks
    gemm_mma<<<dim3(CD / 64, TQN / 128), 256, GSM_BYTES>>>(AO, Wo, bo, out);
}